// round 9
// baseline (speedup 1.0000x reference)
#include <cuda_runtime.h>
#include <cuda_bf16.h>
#include <cuda_fp8.h>
#include <math.h>
#include <stdint.h>

// Problem dims (fixed by the dataset)
#define N_ROWS 32768
#define LATENT 256
#define N_ANCH 4096
#define FDIM   768

#define BM 128
#define BN 128
#define BK 64                      // fp8 elements per k-chunk (64 B/row)
#define NCHUNK (LATENT / BK)       // 4
#define NSTAGE 3
#define THREADS 512

// Screening threshold (log2 domain). fp32 exp is nonzero only for arg2 >
// ~-150. Flag at -170 (conservative: dist^2 < ~236 vs actual min ~254);
// flagged pairs get an exact fp32 recompute from global memory, so
// correctness never depends on fp8 precision. A spurious flag costs only a
// ~768-FMA recompute, no atomics (p underflows to 0 in fp32 too).
#define ETHR (-170.0f)

// SMEM: stage row stride 80 B (64 data + 16 pad). r*80 mod 128 cycles
// through 8 distinct 16B bank-groups -> ldmatrix phases and STS.128
// conflict-free.
#define RSTRIDE_B   80
#define ATILE_B     (BM * RSTRIDE_B)               // 10240
#define STAGE_B     (2 * ATILE_B)                  // 20480 (A then B)
#define SM_OFF_ZQ   0
#define SM_OFF_AQ   512
#define SM_OFF_ST   1024
#define SMEM_DYN    (SM_OFF_ST + NSTAGE * STAGE_B) // 62464 -> occ=2

// Scratch (device globals: allocation-free per harness rules)
__device__ float   g_zsq[N_ROWS];
__device__ float   g_asq[N_ANCH];
__device__ uint8_t g_z8[N_ROWS * LATENT];
__device__ uint8_t g_a8[N_ANCH * LATENT];

__device__ __forceinline__ uint32_t smem_u32(const void* p) {
    uint32_t a;
    asm("{ .reg .u64 t; cvta.to.shared.u64 t, %1; cvt.u32.u64 %0, t; }"
        : "=r"(a) : "l"(p));
    return a;
}
__device__ __forceinline__ void cp_async16(uint32_t dst, const void* src) {
    asm volatile("cp.async.cg.shared.global [%0], [%1], 16;"
                 :: "r"(dst), "l"(src));
}
#define CP_COMMIT() asm volatile("cp.async.commit_group;" ::: "memory")
#define CP_WAITN(n) asm volatile("cp.async.wait_group %0;" :: "n"(n) : "memory")

__device__ __forceinline__ void ldsm_x4(uint32_t& r0, uint32_t& r1,
                                        uint32_t& r2, uint32_t& r3,
                                        uint32_t addr) {
    asm volatile("ldmatrix.sync.aligned.m8n8.x4.shared.b16 {%0,%1,%2,%3}, [%4];"
                 : "=r"(r0), "=r"(r1), "=r"(r2), "=r"(r3) : "r"(addr));
}
// FP8 e4m3 MMA, k=32. Accumulator layout identical to m16n8k16.f16.
__device__ __forceinline__ void mma_fp8(float& c0, float& c1, float& c2, float& c3,
                                        uint32_t a0, uint32_t a1, uint32_t a2, uint32_t a3,
                                        uint32_t b0, uint32_t b1) {
    asm volatile("mma.sync.aligned.m16n8k32.row.col.f32.e4m3.e4m3.f32 "
                 "{%0,%1,%2,%3}, {%4,%5,%6,%7}, {%8,%9}, {%0,%1,%2,%3};"
                 : "+f"(c0), "+f"(c1), "+f"(c2), "+f"(c3)
                 : "r"(a0), "r"(a1), "r"(a2), "r"(a3), "r"(b0), "r"(b1));
}

// ---------------------------------------------------------------------------
__global__ void rkhs_zero_out(float4* __restrict__ out, int nthreads) {
    int i = blockIdx.x * blockDim.x + threadIdx.x;
#pragma unroll
    for (int j = 0; j < 4; j++)
        out[i + j * nthreads] = make_float4(0.f, 0.f, 0.f, 0.f);
}

// ---------------------------------------------------------------------------
// Prepass: fp32 -> fp8(e4m3) + squared norms. One warp per row.
// ---------------------------------------------------------------------------
__global__ void rkhs_prep(const float* __restrict__ z,
                          const float* __restrict__ anch) {
    int gw   = (blockIdx.x * blockDim.x + threadIdx.x) >> 5;
    int lane = threadIdx.x & 31;
    if (gw >= N_ROWS + N_ANCH) return;

    const float* src;
    uint32_t*    dst8;
    float*       dsq;
    if (gw < N_ROWS) {
        src  = z + (size_t)gw * LATENT;
        dst8 = (uint32_t*)(g_z8 + (size_t)gw * LATENT);
        dsq  = &g_zsq[gw];
    } else {
        int r = gw - N_ROWS;
        src  = anch + (size_t)r * LATENT;
        dst8 = (uint32_t*)(g_a8 + (size_t)r * LATENT);
        dsq  = &g_asq[r];
    }

    const float4* p = (const float4*)src;
    float s = 0.f;
#pragma unroll
    for (int i = 0; i < 2; i++) {
        int j = lane + i * 32;                 // float4 index 0..63
        float4 v = p[j];
        s += v.x * v.x + v.y * v.y + v.z * v.z + v.w * v.w;
        __nv_fp8x2_storage_t lo =
            __nv_cvt_float2_to_fp8x2(make_float2(v.x, v.y), __NV_SATFINITE, __NV_E4M3);
        __nv_fp8x2_storage_t hi =
            __nv_cvt_float2_to_fp8x2(make_float2(v.z, v.w), __NV_SATFINITE, __NV_E4M3);
        dst8[j] = (uint32_t)lo | ((uint32_t)hi << 16);
    }
#pragma unroll
    for (int o = 16; o; o >>= 1) s += __shfl_xor_sync(0xffffffffu, s, o);
    if (lane == 0) *dsq = s;
}

// ---------------------------------------------------------------------------
// cp.async loads for k-chunk c into stage s. 1024 16B jobs (512 A + 512 B);
// 2 per thread. Gmem row = 256 B (fp8); chunk = 64 B.
// ---------------------------------------------------------------------------
__device__ __forceinline__ void load_stage(char* smem, int s, int c,
                                           const char* gA, const char* gB,
                                           int tid) {
    char* stA = smem + SM_OFF_ST + s * STAGE_B;
    char* stB = stA + ATILE_B;
    const uint32_t cb = (uint32_t)c * BK;      // 64 B gmem chunk offset
#pragma unroll
    for (int i = 0; i < 2; i++) {
        int job = tid + i * THREADS;           // 0..1023
        int jj  = job & 511;
        int r   = jj >> 2;
        int cc  = jj & 3;
        uint32_t soff = (uint32_t)r * RSTRIDE_B + (uint32_t)cc * 16;
        size_t   goff = (size_t)r * LATENT + cb + (uint32_t)cc * 16;
        if (job < 512) cp_async16(smem_u32(stA + soff), gA + goff);
        else           cp_async16(smem_u32(stB + soff), gB + goff);
    }
}

// ---------------------------------------------------------------------------
// Main: fp8 mma.sync GEMM (128x128x256 per CTA), 3-stage cp.async pipeline
// over 4 K-chunks of 64, + screening epilogue. Warp grid 4x4, tile 32x32.
// ---------------------------------------------------------------------------
__global__ __launch_bounds__(THREADS, 2)
void rkhs_main(const float* __restrict__ z,
               const float* __restrict__ anch,
               const float* __restrict__ alpha,
               const float* __restrict__ logls,
               float* __restrict__ out) {
    extern __shared__ char smem[];
    const uint32_t sb = smem_u32(smem);

    const int m0   = blockIdx.y * BM;
    const int c0   = blockIdx.x * BN;
    const int tid  = threadIdx.x;
    const int wid  = tid >> 5;
    const int lane = tid & 31;
    const int wm   = wid & 3;
    const int wn   = wid >> 2;

    const char* gA = (const char*)(g_z8 + (size_t)m0 * LATENT);
    const char* gB = (const char*)(g_a8 + (size_t)c0 * LATENT);

    // Stage norms (plain LDG/STS; latency overlaps prologue cp.asyncs).
    if (tid < 128)      ((float*)(smem + SM_OFF_ZQ))[tid]       = g_zsq[m0 + tid];
    else if (tid < 256) ((float*)(smem + SM_OFF_AQ))[tid - 128] = g_asq[c0 + tid - 128];

    // Prologue: chunks 0,1,2 into stages 0,1,2.
    load_stage(smem, 0, 0, gA, gB, tid); CP_COMMIT();
    load_stage(smem, 1, 1, gA, gB, tid); CP_COMMIT();
    load_stage(smem, 2, 2, gA, gB, tid); CP_COMMIT();

    // Fragment base offsets within a stage (A then B), RSTRIDE_B=80.
    // fp8 via b16 ldmatrix: a b16 "element" = adjacent fp8 pair; fragment
    // layouts of m16n8k32.e4m3 match m16n8k16.f16 exactly.
    const uint32_t aOff = (uint32_t)(wm * 32 + (lane & 15)) * RSTRIDE_B
                        + (uint32_t)(lane >> 4) * 16;
    const uint32_t bOff = (uint32_t)(wn * 32 + ((lane >> 4) << 3) + (lane & 7)) * RSTRIDE_B
                        + (uint32_t)((lane >> 3) & 1) * 16;

    float c[2][4][4];
#pragma unroll
    for (int mi = 0; mi < 2; mi++)
#pragma unroll
        for (int ni = 0; ni < 4; ni++)
#pragma unroll
            for (int q = 0; q < 4; q++) c[mi][ni][q] = 0.f;

#pragma unroll
    for (int ch = 0; ch < NCHUNK; ch++) {
        // Group completion: need group ch done.
        if (ch == 0)      CP_WAITN(2);
        else if (ch == 1) CP_WAITN(1);
        else if (ch == 2) CP_WAITN(1);
        else              CP_WAITN(0);
        __syncthreads();   // also fences: all warps past chunk ch-1 reads

        // Prefetch chunk 3 into stage 0 once chunk 0's readers are done.
        if (ch == 1) {
            load_stage(smem, 0, 3, gA, gB, tid);
            CP_COMMIT();
        }

        const uint32_t stA = sb + SM_OFF_ST + (uint32_t)(ch % NSTAGE) * STAGE_B;
        const uint32_t stB = stA + ATILE_B;
        const uint32_t aB  = stA + aOff;
        const uint32_t bB  = stB + bOff;

#pragma unroll
        for (int kt = 0; kt < BK / 32; kt++) {     // 2 k32-steps per chunk
            const uint32_t ko = (uint32_t)kt * 32; // 32 fp8 = 32 B
            uint32_t a[2][4], b[2][4];
            ldsm_x4(a[0][0], a[0][1], a[0][2], a[0][3], aB + ko);
            ldsm_x4(a[1][0], a[1][1], a[1][2], a[1][3], aB + ko + 16u * RSTRIDE_B);
            ldsm_x4(b[0][0], b[0][1], b[0][2], b[0][3], bB + ko);
            ldsm_x4(b[1][0], b[1][1], b[1][2], b[1][3], bB + ko + 16u * RSTRIDE_B);
#pragma unroll
            for (int mi = 0; mi < 2; mi++)
#pragma unroll
                for (int ni = 0; ni < 4; ni++)
                    mma_fp8(c[mi][ni][0], c[mi][ni][1], c[mi][ni][2], c[mi][ni][3],
                            a[mi][0], a[mi][1], a[mi][2], a[mi][3],
                            b[ni >> 1][(ni & 1) * 2], b[ni >> 1][(ni & 1) * 2 + 1]);
        }
    }

    // --- Screening epilogue (acc: row = lane>>2 (+8 q>=2), col = 2*(lane&3) (+1 odd q)) ---
    const float lsv = logls[0];
    const float l   = expf(lsv);
    const float il2 = 1.0f / (l * l + 1e-7f);
    const float c2f = -0.5f * 1.44269504088896340736f * il2;

    const float* sZq = (const float*)(smem + SM_OFF_ZQ);
    const float* sAq = (const float*)(smem + SM_OFF_AQ);
    const int rBase = wm * 32 + (lane >> 2);
    const int nBase = wn * 32 + 2 * (lane & 3);

    int any_local = 0;
#pragma unroll
    for (int mi = 0; mi < 2; mi++) {
        float zq0 = sZq[rBase + mi * 16];
        float zq1 = sZq[rBase + mi * 16 + 8];
#pragma unroll
        for (int ni = 0; ni < 4; ni++) {
            float aq0 = sAq[nBase + ni * 8];
            float aq1 = sAq[nBase + ni * 8 + 1];
            float e0 = c2f * (zq0 + aq0 - 2.f * c[mi][ni][0]);
            float e1 = c2f * (zq0 + aq1 - 2.f * c[mi][ni][1]);
            float e2 = c2f * (zq1 + aq0 - 2.f * c[mi][ni][2]);
            float e3 = c2f * (zq1 + aq1 - 2.f * c[mi][ni][3]);
            any_local |= (e0 > ETHR) | (e1 > ETHR) | (e2 > ETHR) | (e3 > ETHR);
        }
    }

    // Expected: essentially never flags (dist^2 min ~254 > screen ~236).
    if (!__syncthreads_or(any_local)) return;

    // Exact fp32 fallback for flagged pairs (cold; correctness-exact).
#pragma unroll 1
    for (int mi = 0; mi < 2; mi++) {
#pragma unroll 1
        for (int ni = 0; ni < 4; ni++) {
#pragma unroll 1
            for (int q = 0; q < 4; q++) {
                int rl = rBase + mi * 16 + (q >> 1) * 8;
                int nl = nBase + ni * 8 + (q & 1);
                float e = c2f * (sZq[rl] + sAq[nl] - 2.f * c[mi][ni][q]);
                if (e > ETHR) {
                    int gr = m0 + rl;
                    int gc = c0 + nl;
                    const float* zr = z    + (size_t)gr * LATENT;
                    const float* ar = anch + (size_t)gc * LATENT;
                    float dot = 0.f, zq = 0.f, aq = 0.f;
                    for (int k = 0; k < LATENT; k++) {
                        dot = fmaf(zr[k], ar[k], dot);
                        zq  = fmaf(zr[k], zr[k], zq);
                        aq  = fmaf(ar[k], ar[k], aq);
                    }
                    float de = fmaxf(zq + aq - 2.f * dot, 0.f);
                    float p  = expf(-0.5f * de * il2);
                    if (p != 0.f) {
                        const float* al = alpha + (size_t)gc * FDIM;
                        float*       o  = out   + (size_t)gr * FDIM;
                        for (int f = 0; f < FDIM; f++) atomicAdd(&o[f], p * al[f]);
                    }
                }
            }
        }
    }
}

// ---------------------------------------------------------------------------
extern "C" void kernel_launch(void* const* d_in, const int* in_sizes, int n_in,
                              void* d_out, int out_size) {
    const float* z     = (const float*)d_in[0];
    const float* anch  = (const float*)d_in[1];
    const float* alpha = (const float*)d_in[2];
    const float* logls = (const float*)d_in[3];
    float*       out   = (float*)d_out;

    cudaFuncSetAttribute(rkhs_main,
                         cudaFuncAttributeMaxDynamicSharedMemorySize, SMEM_DYN);

    // out_size = 32768*768 = 25165824 floats = 6291456 float4 = 4 * 1572864
    int nthreads = out_size / 16;              // threads, 4 float4 each
    rkhs_zero_out<<<nthreads / 256, 256>>>((float4*)d_out, nthreads);

    int nwarps  = N_ROWS + N_ANCH;
    int nblocks = (nwarps * 32 + 255) / 256;
    rkhs_prep<<<nblocks, 256>>>(z, anch);

    dim3 grid(N_ANCH / BN, N_ROWS / BM);       // (32, 256)
    rkhs_main<<<grid, THREADS, SMEM_DYN>>>(z, anch, alpha, logls, out);
}

// round 10
// speedup vs baseline: 1.0126x; 1.0126x over previous
#include <cuda_runtime.h>
#include <cuda_bf16.h>
#include <math.h>
#include <stdint.h>

// Problem dims (fixed by the dataset)
#define N_ROWS 32768
#define LATENT 256
#define FDIM   768
#define N_ANCH 4096

// Screening GEMM uses only the first KP=192 latent dims: dist^2 over a
// coordinate subset is a LOWER bound on the full dist^2, and the exponent
// scale c2f is negative for every lengthscale, so e_partial >= e_full and
// the screen below remains unconditionally conservative.
#define KP 192
#define BM 128
#define BN 128
#define BK 64                      // bf16 per k-chunk (128 B/row)
#define NCHUNK (KP / BK)           // 3
#define THREADS 256

// Flag if e_partial > -170 (log2 domain; fp32 exp nonzero needs e_full >
// ~-150). Flagged pairs get an exact fp32 recompute over ALL 256 dims from
// global memory, so correctness never depends on bf16 or the truncation.
#define ETHR (-170.0f)

// SMEM: row stride 72 bf16 = 144 B -> ldmatrix phases + STS.128 conflict-free.
#define RSTRIDE_B   144
#define ATILE_B     (BM * RSTRIDE_B)           // 18432
#define STAGE_B     (2 * ATILE_B)              // 36864 (A then B)
#define SM_OFF_ZQ   0
#define SM_OFF_AQ   512
#define SM_OFF_ST   1024
#define SMEM_DYN    (SM_OFF_ST + 2 * STAGE_B)  // 74752 -> occ=2

// Scratch: bf16 rows hold only the first KP dims (row stride 192 bf16 = 384B).
__device__ float         g_zsq[N_ROWS];        // partial (KP-dim) sq-norms
__device__ float         g_asq[N_ANCH];
__device__ __nv_bfloat16 g_zb[(size_t)N_ROWS * KP];
__device__ __nv_bfloat16 g_ab[(size_t)N_ANCH * KP];

__device__ __forceinline__ uint32_t smem_u32(const void* p) {
    uint32_t a;
    asm("{ .reg .u64 t; cvta.to.shared.u64 t, %1; cvt.u32.u64 %0, t; }"
        : "=r"(a) : "l"(p));
    return a;
}
__device__ __forceinline__ void cp_async16(uint32_t dst, const void* src) {
    asm volatile("cp.async.cg.shared.global [%0], [%1], 16;"
                 :: "r"(dst), "l"(src));
}
#define CP_COMMIT() asm volatile("cp.async.commit_group;" ::: "memory")
#define CP_WAITN(n) asm volatile("cp.async.wait_group %0;" :: "n"(n) : "memory")

__device__ __forceinline__ void ldsm_x4(uint32_t& r0, uint32_t& r1,
                                        uint32_t& r2, uint32_t& r3,
                                        uint32_t addr) {
    asm volatile("ldmatrix.sync.aligned.m8n8.x4.shared.b16 {%0,%1,%2,%3}, [%4];"
                 : "=r"(r0), "=r"(r1), "=r"(r2), "=r"(r3) : "r"(addr));
}
__device__ __forceinline__ void mma_16816(float& c0, float& c1, float& c2, float& c3,
                                          uint32_t a0, uint32_t a1, uint32_t a2, uint32_t a3,
                                          uint32_t b0, uint32_t b1) {
    asm volatile("mma.sync.aligned.m16n8k16.row.col.f32.bf16.bf16.f32 "
                 "{%0,%1,%2,%3}, {%4,%5,%6,%7}, {%8,%9}, {%0,%1,%2,%3};"
                 : "+f"(c0), "+f"(c1), "+f"(c2), "+f"(c3)
                 : "r"(a0), "r"(a1), "r"(a2), "r"(a3), "r"(b0), "r"(b1));
}

// ---------------------------------------------------------------------------
__global__ void rkhs_zero_out(float4* __restrict__ out, int nthreads) {
    int i = blockIdx.x * blockDim.x + threadIdx.x;
#pragma unroll
    for (int j = 0; j < 4; j++)
        out[i + j * nthreads] = make_float4(0.f, 0.f, 0.f, 0.f);
}

// ---------------------------------------------------------------------------
// Prepass: fp32 -> bf16 for the first KP dims + partial sq-norm. Warp/row.
// ---------------------------------------------------------------------------
__global__ void rkhs_prep(const float* __restrict__ z,
                          const float* __restrict__ anch) {
    int gw   = (blockIdx.x * blockDim.x + threadIdx.x) >> 5;
    int lane = threadIdx.x & 31;
    if (gw >= N_ROWS + N_ANCH) return;

    const float*    src;
    __nv_bfloat162* dstb;
    float*          dsq;
    if (gw < N_ROWS) {
        src  = z + (size_t)gw * LATENT;
        dstb = (__nv_bfloat162*)(g_zb + (size_t)gw * KP);
        dsq  = &g_zsq[gw];
    } else {
        int r = gw - N_ROWS;
        src  = anch + (size_t)r * LATENT;
        dstb = (__nv_bfloat162*)(g_ab + (size_t)r * KP);
        dsq  = &g_asq[r];
    }

    const float4* p = (const float4*)src;
    float s = 0.f;
#pragma unroll
    for (int i = 0; i < 2; i++) {
        int j = lane + i * 32;                  // float4 index
        if (j < KP / 4) {                       // first 48 of 64
            float4 v = p[j];
            s += v.x * v.x + v.y * v.y + v.z * v.z + v.w * v.w;
            dstb[2 * j + 0] = __floats2bfloat162_rn(v.x, v.y);
            dstb[2 * j + 1] = __floats2bfloat162_rn(v.z, v.w);
        }
    }
#pragma unroll
    for (int o = 16; o; o >>= 1) s += __shfl_xor_sync(0xffffffffu, s, o);
    if (lane == 0) *dsq = s;
}

// ---------------------------------------------------------------------------
// cp.async: k-chunk c -> stage s. 2048 16B jobs (1024 A + 1024 B); 8/thread.
// Gmem bf16 row = KP*2 = 384 B; chunk = 128 B.
// ---------------------------------------------------------------------------
__device__ __forceinline__ void load_stage(char* smem, int s, int c,
                                           const char* gA, const char* gB,
                                           int tid) {
    char* stA = smem + SM_OFF_ST + s * STAGE_B;
    char* stB = stA + ATILE_B;
    const uint32_t cb = (uint32_t)c * (BK * 2);   // 128 B chunk offset
#pragma unroll
    for (int i = 0; i < 8; i++) {
        int job = tid + i * THREADS;              // 0..2047
        int jj  = job & 1023;
        int r   = jj >> 3;
        int cc  = jj & 7;
        uint32_t soff = (uint32_t)r * RSTRIDE_B + (uint32_t)cc * 16;
        size_t   goff = (size_t)r * (KP * 2) + cb + (uint32_t)cc * 16;
        if (job < 1024) cp_async16(smem_u32(stA + soff), gA + goff);
        else            cp_async16(smem_u32(stB + soff), gB + goff);
    }
}

// ---------------------------------------------------------------------------
// Main: bf16 mma.sync screening GEMM (128x128x192 per CTA), 2-stage cp.async
// pipeline, warp grid 2(m)x4(n), warp tile 64x32.
// ---------------------------------------------------------------------------
__global__ __launch_bounds__(THREADS, 2)
void rkhs_main(const float* __restrict__ z,
               const float* __restrict__ anch,
               const float* __restrict__ alpha,
               const float* __restrict__ logls,
               float* __restrict__ out) {
    extern __shared__ char smem[];
    const uint32_t sb = smem_u32(smem);

    const int m0   = blockIdx.y * BM;
    const int c0   = blockIdx.x * BN;
    const int tid  = threadIdx.x;
    const int wid  = tid >> 5;
    const int lane = tid & 31;
    const int wm   = wid & 1;           // m-block (64 rows)
    const int wn   = wid >> 1;          // n-block (32 cols)

    const char* gA = (const char*)(g_zb + (size_t)m0 * KP);
    const char* gB = (const char*)(g_ab + (size_t)c0 * KP);

    // Stage norms (latency overlaps prologue cp.asyncs).
    if (tid < 128) ((float*)(smem + SM_OFF_ZQ))[tid]       = g_zsq[m0 + tid];
    else           ((float*)(smem + SM_OFF_AQ))[tid - 128] = g_asq[c0 + tid - 128];

    // Prologue: chunks 0,1 -> stages 0,1.
    load_stage(smem, 0, 0, gA, gB, tid); CP_COMMIT();
    load_stage(smem, 1, 1, gA, gB, tid); CP_COMMIT();

    const uint32_t aOff = (uint32_t)(wm * 64 + (lane & 15)) * RSTRIDE_B
                        + (uint32_t)(lane >> 4) * 16;
    const uint32_t bOff = (uint32_t)(wn * 32 + ((lane >> 4) << 3) + (lane & 7)) * RSTRIDE_B
                        + (uint32_t)((lane >> 3) & 1) * 16;

    float c[4][4][4];
#pragma unroll
    for (int mi = 0; mi < 4; mi++)
#pragma unroll
        for (int ni = 0; ni < 4; ni++)
#pragma unroll
            for (int q = 0; q < 4; q++) c[mi][ni][q] = 0.f;

#pragma unroll
    for (int ch = 0; ch < NCHUNK; ch++) {
        if (ch < NCHUNK - 1) CP_WAITN(1); else CP_WAITN(0);
        __syncthreads();

        const uint32_t stA = sb + SM_OFF_ST + (uint32_t)(ch & 1) * STAGE_B;
        const uint32_t stB = stA + ATILE_B;
        const uint32_t aB  = stA + aOff;
        const uint32_t bB  = stB + bOff;

#pragma unroll
        for (int kt = 0; kt < BK / 16; kt++) {
            const uint32_t ko = (uint32_t)kt * 32;
            uint32_t a[4][4], b[2][4];
#pragma unroll
            for (int mi = 0; mi < 4; mi++)
                ldsm_x4(a[mi][0], a[mi][1], a[mi][2], a[mi][3],
                        aB + ko + (uint32_t)mi * 16u * RSTRIDE_B);
            ldsm_x4(b[0][0], b[0][1], b[0][2], b[0][3], bB + ko);
            ldsm_x4(b[1][0], b[1][1], b[1][2], b[1][3], bB + ko + 16u * RSTRIDE_B);
#pragma unroll
            for (int mi = 0; mi < 4; mi++)
#pragma unroll
                for (int ni = 0; ni < 4; ni++)
                    mma_16816(c[mi][ni][0], c[mi][ni][1], c[mi][ni][2], c[mi][ni][3],
                              a[mi][0], a[mi][1], a[mi][2], a[mi][3],
                              b[ni >> 1][(ni & 1) * 2], b[ni >> 1][(ni & 1) * 2 + 1]);
        }

        if (ch + 2 < NCHUNK) {
            __syncthreads();
            load_stage(smem, ch & 1, ch + 2, gA, gB, tid);
            CP_COMMIT();
        }
    }

    // --- Screening epilogue (partial-dim lower bound; conservative for any l) ---
    const float lsv = logls[0];
    const float l   = expf(lsv);
    const float il2 = 1.0f / (l * l + 1e-7f);
    const float c2f = -0.5f * 1.44269504088896340736f * il2;

    const float* sZq = (const float*)(smem + SM_OFF_ZQ);
    const float* sAq = (const float*)(smem + SM_OFF_AQ);
    const int rBase = wm * 64 + (lane >> 2);
    const int nBase = wn * 32 + 2 * (lane & 3);

    int any_local = 0;
#pragma unroll
    for (int mi = 0; mi < 4; mi++) {
        float zq0 = sZq[rBase + mi * 16];
        float zq1 = sZq[rBase + mi * 16 + 8];
#pragma unroll
        for (int ni = 0; ni < 4; ni++) {
            float aq0 = sAq[nBase + ni * 8];
            float aq1 = sAq[nBase + ni * 8 + 1];
            float e0 = c2f * (zq0 + aq0 - 2.f * c[mi][ni][0]);
            float e1 = c2f * (zq0 + aq1 - 2.f * c[mi][ni][1]);
            float e2 = c2f * (zq1 + aq0 - 2.f * c[mi][ni][2]);
            float e3 = c2f * (zq1 + aq1 - 2.f * c[mi][ni][3]);
            any_local |= (e0 > ETHR) | (e1 > ETHR) | (e2 > ETHR) | (e3 > ETHR);
        }
    }

    // ~6e-6 flag rate (2*chi2_192 left tail) -> virtually every CTA exits.
    if (!__syncthreads_or(any_local)) return;

    // Exact fp32 fallback over ALL 256 dims for flagged pairs (cold path).
#pragma unroll 1
    for (int mi = 0; mi < 4; mi++) {
#pragma unroll 1
        for (int ni = 0; ni < 4; ni++) {
#pragma unroll 1
            for (int q = 0; q < 4; q++) {
                int rl = rBase + mi * 16 + (q >> 1) * 8;
                int nl = nBase + ni * 8 + (q & 1);
                float e = c2f * (sZq[rl] + sAq[nl] - 2.f * c[mi][ni][q]);
                if (e > ETHR) {
                    int gr = m0 + rl;
                    int gc = c0 + nl;
                    const float* zr = z    + (size_t)gr * LATENT;
                    const float* ar = anch + (size_t)gc * LATENT;
                    float dot = 0.f, zq = 0.f, aq = 0.f;
                    for (int k = 0; k < LATENT; k++) {
                        dot = fmaf(zr[k], ar[k], dot);
                        zq  = fmaf(zr[k], zr[k], zq);
                        aq  = fmaf(ar[k], ar[k], aq);
                    }
                    float de = fmaxf(zq + aq - 2.f * dot, 0.f);
                    float p  = expf(-0.5f * de * il2);
                    if (p != 0.f) {
                        const float* al = alpha + (size_t)gc * FDIM;
                        float*       o  = out   + (size_t)gr * FDIM;
                        for (int f = 0; f < FDIM; f++) atomicAdd(&o[f], p * al[f]);
                    }
                }
            }
        }
    }
}

// ---------------------------------------------------------------------------
extern "C" void kernel_launch(void* const* d_in, const int* in_sizes, int n_in,
                              void* d_out, int out_size) {
    const float* z     = (const float*)d_in[0];
    const float* anch  = (const float*)d_in[1];
    const float* alpha = (const float*)d_in[2];
    const float* logls = (const float*)d_in[3];
    float*       out   = (float*)d_out;

    cudaFuncSetAttribute(rkhs_main,
                         cudaFuncAttributeMaxDynamicSharedMemorySize, SMEM_DYN);

    int nthreads = out_size / 16;              // 4 float4 per thread
    rkhs_zero_out<<<nthreads / 256, 256>>>((float4*)d_out, nthreads);

    int nwarps  = N_ROWS + N_ANCH;
    int nblocks = (nwarps * 32 + 255) / 256;
    rkhs_prep<<<nblocks, 256>>>(z, anch);

    dim3 grid(N_ANCH / BN, N_ROWS / BM);       // (32, 256)
    rkhs_main<<<grid, THREADS, SMEM_DYN>>>(z, anch, alpha, logls, out);
}

// round 11
// speedup vs baseline: 1.2669x; 1.2511x over previous
#include <cuda_runtime.h>
#include <cuda_bf16.h>
#include <math.h>
#include <stdint.h>

// Problem dims (fixed by the dataset)
#define N_ROWS 32768
#define LATENT 256
#define N_ANCH 4096
#define FDIM   768

// Screening GEMM uses only the first KP=192 latent dims: dist^2 over a
// coordinate subset is a LOWER bound on the full dist^2, and the exponent
// scale c2f is negative for every lengthscale, so e_partial >= e_full and
// the screen is unconditionally conservative.
#define KP 192
#define BM 128
#define BN 128
#define BK 64                      // bf16 per k-chunk (128 B/row)
#define NCHUNK (KP / BK)           // 3
#define THREADS 512

// Flag if e_partial > -170 (log2 domain; fp32 exp nonzero needs e_full >
// ~-150). Flagged pairs get an exact fp32 recompute over ALL 256 dims.
#define ETHR (-170.0f)

// SMEM: row stride 72 bf16 = 144 B -> ldmatrix phases + STS.128 conflict-free.
#define RSTRIDE_B   144
#define ATILE_B     (BM * RSTRIDE_B)           // 18432
#define STAGE_B     (2 * ATILE_B)              // 36864 (A then B)
#define SM_OFF_ZQ   0
#define SM_OFF_AQ   512
#define SM_OFF_ST   1024
#define SMEM_DYN    (SM_OFF_ST + 2 * STAGE_B)  // 74752 -> occ=2

// Scratch: bf16 rows hold only the first KP dims (row stride 384 B).
__device__ float         g_zsq[N_ROWS];        // partial (KP-dim) sq-norms
__device__ float         g_asq[N_ANCH];
__device__ __nv_bfloat16 g_zb[(size_t)N_ROWS * KP];
__device__ __nv_bfloat16 g_ab[(size_t)N_ANCH * KP];

__device__ __forceinline__ uint32_t smem_u32(const void* p) {
    uint32_t a;
    asm("{ .reg .u64 t; cvta.to.shared.u64 t, %1; cvt.u32.u64 %0, t; }"
        : "=r"(a) : "l"(p));
    return a;
}
__device__ __forceinline__ void cp_async16(uint32_t dst, const void* src) {
    asm volatile("cp.async.cg.shared.global [%0], [%1], 16;"
                 :: "r"(dst), "l"(src));
}
#define CP_COMMIT() asm volatile("cp.async.commit_group;" ::: "memory")
#define CP_WAITN(n) asm volatile("cp.async.wait_group %0;" :: "n"(n) : "memory")

__device__ __forceinline__ void ldsm_x4(uint32_t& r0, uint32_t& r1,
                                        uint32_t& r2, uint32_t& r3,
                                        uint32_t addr) {
    asm volatile("ldmatrix.sync.aligned.m8n8.x4.shared.b16 {%0,%1,%2,%3}, [%4];"
                 : "=r"(r0), "=r"(r1), "=r"(r2), "=r"(r3) : "r"(addr));
}
__device__ __forceinline__ void mma_16816(float& c0, float& c1, float& c2, float& c3,
                                          uint32_t a0, uint32_t a1, uint32_t a2, uint32_t a3,
                                          uint32_t b0, uint32_t b1) {
    asm volatile("mma.sync.aligned.m16n8k16.row.col.f32.bf16.bf16.f32 "
                 "{%0,%1,%2,%3}, {%4,%5,%6,%7}, {%8,%9}, {%0,%1,%2,%3};"
                 : "+f"(c0), "+f"(c1), "+f"(c2), "+f"(c3)
                 : "r"(a0), "r"(a1), "r"(a2), "r"(a3), "r"(b0), "r"(b1));
}

// ---------------------------------------------------------------------------
__global__ void rkhs_zero_out(float4* __restrict__ out, int nthreads) {
    int i = blockIdx.x * blockDim.x + threadIdx.x;
#pragma unroll
    for (int j = 0; j < 4; j++)
        out[i + j * nthreads] = make_float4(0.f, 0.f, 0.f, 0.f);
}

// ---------------------------------------------------------------------------
// Prepass: fp32 -> bf16 for the first KP dims + partial sq-norm. Warp/row.
// ---------------------------------------------------------------------------
__global__ void rkhs_prep(const float* __restrict__ z,
                          const float* __restrict__ anch) {
    int gw   = (blockIdx.x * blockDim.x + threadIdx.x) >> 5;
    int lane = threadIdx.x & 31;
    if (gw >= N_ROWS + N_ANCH) return;

    const float*    src;
    __nv_bfloat162* dstb;
    float*          dsq;
    if (gw < N_ROWS) {
        src  = z + (size_t)gw * LATENT;
        dstb = (__nv_bfloat162*)(g_zb + (size_t)gw * KP);
        dsq  = &g_zsq[gw];
    } else {
        int r = gw - N_ROWS;
        src  = anch + (size_t)r * LATENT;
        dstb = (__nv_bfloat162*)(g_ab + (size_t)r * KP);
        dsq  = &g_asq[r];
    }

    const float4* p = (const float4*)src;
    float s = 0.f;
#pragma unroll
    for (int i = 0; i < 2; i++) {
        int j = lane + i * 32;                  // float4 index
        if (j < KP / 4) {                       // first 48 of 64
            float4 v = p[j];
            s += v.x * v.x + v.y * v.y + v.z * v.z + v.w * v.w;
            dstb[2 * j + 0] = __floats2bfloat162_rn(v.x, v.y);
            dstb[2 * j + 1] = __floats2bfloat162_rn(v.z, v.w);
        }
    }
#pragma unroll
    for (int o = 16; o; o >>= 1) s += __shfl_xor_sync(0xffffffffu, s, o);
    if (lane == 0) *dsq = s;
}

// ---------------------------------------------------------------------------
// cp.async: k-chunk c -> stage s. 2048 16B jobs (1024 A + 1024 B); 4/thread.
// Gmem bf16 row = KP*2 = 384 B; chunk = 128 B.
// ---------------------------------------------------------------------------
__device__ __forceinline__ void load_stage(char* smem, int s, int c,
                                           const char* gA, const char* gB,
                                           int tid) {
    char* stA = smem + SM_OFF_ST + s * STAGE_B;
    char* stB = stA + ATILE_B;
    const uint32_t cb = (uint32_t)c * (BK * 2);   // 128 B chunk offset
#pragma unroll
    for (int i = 0; i < 4; i++) {
        int job = tid + i * THREADS;              // 0..2047
        int jj  = job & 1023;
        int r   = jj >> 3;
        int cc  = jj & 7;
        uint32_t soff = (uint32_t)r * RSTRIDE_B + (uint32_t)cc * 16;
        size_t   goff = (size_t)r * (KP * 2) + cb + (uint32_t)cc * 16;
        if (job < 1024) cp_async16(smem_u32(stA + soff), gA + goff);
        else            cp_async16(smem_u32(stB + soff), gB + goff);
    }
}

// ---------------------------------------------------------------------------
// Main: bf16 mma.sync screening GEMM (128x128x192 per CTA), 2-stage cp.async
// pipeline over 3 K-chunks of 64. Warp grid 4x4, warp tile 32x32 (the R8
// shape: 16 warps/CTA x occ 2 = 32 warps/SM keeps HMMA issue saturated).
// ---------------------------------------------------------------------------
__global__ __launch_bounds__(THREADS, 2)
void rkhs_main(const float* __restrict__ z,
               const float* __restrict__ anch,
               const float* __restrict__ alpha,
               const float* __restrict__ logls,
               float* __restrict__ out) {
    extern __shared__ char smem[];
    const uint32_t sb = smem_u32(smem);

    const int m0   = blockIdx.y * BM;
    const int c0   = blockIdx.x * BN;
    const int tid  = threadIdx.x;
    const int wid  = tid >> 5;
    const int lane = tid & 31;
    const int wm   = wid & 3;
    const int wn   = wid >> 2;

    const char* gA = (const char*)(g_zb + (size_t)m0 * KP);
    const char* gB = (const char*)(g_ab + (size_t)c0 * KP);

    // Stage norms (latency overlaps prologue cp.asyncs).
    if (tid < 128)      ((float*)(smem + SM_OFF_ZQ))[tid]       = g_zsq[m0 + tid];
    else if (tid < 256) ((float*)(smem + SM_OFF_AQ))[tid - 128] = g_asq[c0 + tid - 128];

    // Prologue: chunks 0,1 -> stages 0,1.
    load_stage(smem, 0, 0, gA, gB, tid); CP_COMMIT();
    load_stage(smem, 1, 1, gA, gB, tid); CP_COMMIT();

    const uint32_t aOff = (uint32_t)(wm * 32 + (lane & 15)) * RSTRIDE_B
                        + (uint32_t)(lane >> 4) * 16;
    const uint32_t bOff = (uint32_t)(wn * 32 + ((lane >> 4) << 3) + (lane & 7)) * RSTRIDE_B
                        + (uint32_t)((lane >> 3) & 1) * 16;

    float c[2][4][4];
#pragma unroll
    for (int mi = 0; mi < 2; mi++)
#pragma unroll
        for (int ni = 0; ni < 4; ni++)
#pragma unroll
            for (int q = 0; q < 4; q++) c[mi][ni][q] = 0.f;

#pragma unroll
    for (int ch = 0; ch < NCHUNK; ch++) {
        if (ch < NCHUNK - 1) CP_WAITN(1); else CP_WAITN(0);
        __syncthreads();

        const uint32_t stA = sb + SM_OFF_ST + (uint32_t)(ch & 1) * STAGE_B;
        const uint32_t stB = stA + ATILE_B;
        const uint32_t aB  = stA + aOff;
        const uint32_t bB  = stB + bOff;

#pragma unroll
        for (int kt = 0; kt < BK / 16; kt++) {
            const uint32_t ko = (uint32_t)kt * 32;
            uint32_t a[2][4], b[2][4];
            ldsm_x4(a[0][0], a[0][1], a[0][2], a[0][3], aB + ko);
            ldsm_x4(a[1][0], a[1][1], a[1][2], a[1][3], aB + ko + 16u * RSTRIDE_B);
            ldsm_x4(b[0][0], b[0][1], b[0][2], b[0][3], bB + ko);
            ldsm_x4(b[1][0], b[1][1], b[1][2], b[1][3], bB + ko + 16u * RSTRIDE_B);
#pragma unroll
            for (int mi = 0; mi < 2; mi++)
#pragma unroll
                for (int ni = 0; ni < 4; ni++)
                    mma_16816(c[mi][ni][0], c[mi][ni][1], c[mi][ni][2], c[mi][ni][3],
                              a[mi][0], a[mi][1], a[mi][2], a[mi][3],
                              b[ni >> 1][(ni & 1) * 2], b[ni >> 1][(ni & 1) * 2 + 1]);
        }

        if (ch + 2 < NCHUNK) {
            __syncthreads();   // all warps done reading this stage
            load_stage(smem, ch & 1, ch + 2, gA, gB, tid);
            CP_COMMIT();
        }
    }

    // --- Screening epilogue (partial-dim lower bound; conservative for any l) ---
    const float lsv = logls[0];
    const float l   = expf(lsv);
    const float il2 = 1.0f / (l * l + 1e-7f);
    const float c2f = -0.5f * 1.44269504088896340736f * il2;

    const float* sZq = (const float*)(smem + SM_OFF_ZQ);
    const float* sAq = (const float*)(smem + SM_OFF_AQ);
    const int rBase = wm * 32 + (lane >> 2);
    const int nBase = wn * 32 + 2 * (lane & 3);

    int any_local = 0;
#pragma unroll
    for (int mi = 0; mi < 2; mi++) {
        float zq0 = sZq[rBase + mi * 16];
        float zq1 = sZq[rBase + mi * 16 + 8];
#pragma unroll
        for (int ni = 0; ni < 4; ni++) {
            float aq0 = sAq[nBase + ni * 8];
            float aq1 = sAq[nBase + ni * 8 + 1];
            float e0 = c2f * (zq0 + aq0 - 2.f * c[mi][ni][0]);
            float e1 = c2f * (zq0 + aq1 - 2.f * c[mi][ni][1]);
            float e2 = c2f * (zq1 + aq0 - 2.f * c[mi][ni][2]);
            float e3 = c2f * (zq1 + aq1 - 2.f * c[mi][ni][3]);
            any_local |= (e0 > ETHR) | (e1 > ETHR) | (e2 > ETHR) | (e3 > ETHR);
        }
    }

    // ~6e-6 flag rate (2*chi2_192 left tail) -> virtually every CTA exits.
    if (!__syncthreads_or(any_local)) return;

    // Exact fp32 fallback over ALL 256 dims for flagged pairs (cold path).
#pragma unroll 1
    for (int mi = 0; mi < 2; mi++) {
#pragma unroll 1
        for (int ni = 0; ni < 4; ni++) {
#pragma unroll 1
            for (int q = 0; q < 4; q++) {
                int rl = rBase + mi * 16 + (q >> 1) * 8;
                int nl = nBase + ni * 8 + (q & 1);
                float e = c2f * (sZq[rl] + sAq[nl] - 2.f * c[mi][ni][q]);
                if (e > ETHR) {
                    int gr = m0 + rl;
                    int gc = c0 + nl;
                    const float* zr = z    + (size_t)gr * LATENT;
                    const float* ar = anch + (size_t)gc * LATENT;
                    float dot = 0.f, zq = 0.f, aq = 0.f;
                    for (int k = 0; k < LATENT; k++) {
                        dot = fmaf(zr[k], ar[k], dot);
                        zq  = fmaf(zr[k], zr[k], zq);
                        aq  = fmaf(ar[k], ar[k], aq);
                    }
                    float de = fmaxf(zq + aq - 2.f * dot, 0.f);
                    float p  = expf(-0.5f * de * il2);
                    if (p != 0.f) {
                        const float* al = alpha + (size_t)gc * FDIM;
                        float*       o  = out   + (size_t)gr * FDIM;
                        for (int f = 0; f < FDIM; f++) atomicAdd(&o[f], p * al[f]);
                    }
                }
            }
        }
    }
}

// ---------------------------------------------------------------------------
extern "C" void kernel_launch(void* const* d_in, const int* in_sizes, int n_in,
                              void* d_out, int out_size) {
    const float* z     = (const float*)d_in[0];
    const float* anch  = (const float*)d_in[1];
    const float* alpha = (const float*)d_in[2];
    const float* logls = (const float*)d_in[3];
    float*       out   = (float*)d_out;

    cudaFuncSetAttribute(rkhs_main,
                         cudaFuncAttributeMaxDynamicSharedMemorySize, SMEM_DYN);

    int nthreads = out_size / 16;              // 4 float4 per thread
    rkhs_zero_out<<<nthreads / 256, 256>>>((float4*)d_out, nthreads);

    int nwarps  = N_ROWS + N_ANCH;
    int nblocks = (nwarps * 32 + 255) / 256;
    rkhs_prep<<<nblocks, 256>>>(z, anch);

    dim3 grid(N_ANCH / BN, N_ROWS / BM);       // (32, 256)
    rkhs_main<<<grid, THREADS, SMEM_DYN>>>(z, anch, alpha, logls, out);
}